// round 11
// baseline (speedup 1.0000x reference)
#include <cuda_runtime.h>
#include <cstdint>

#define B_  4
#define S_  2048
#define D_  1024
#define H_  16
#define DK_ 64
#define M_  (B_ * S_)                    // 8192
#define QKV_ELEMS (B_ * H_ * S_ * DK_)   // 8388608

// Scratch (device globals; no runtime allocation)
__device__ float g_Q[QKV_ELEMS];
__device__ float g_K[QKV_ELEMS];
__device__ float g_V[QKV_ELEMS];
__device__ float g_O[QKV_ELEMS];
__device__ float g_WT[3 * D_ * D_];      // W^T for Q,K,V: [z][j][d]
__device__ float g_WoT[D_ * D_];         // Wo^T: [n][j]

// ---------------------------------------------------------------------------
// Helpers (base-ISA only: mma.sync + cp.async)
// ---------------------------------------------------------------------------
__device__ __forceinline__ uint32_t smem_u32(const void* p) {
    uint32_t a;
    asm("{ .reg .u64 t; cvta.to.shared.u64 t, %1; cvt.u32.u64 %0, t; }"
        : "=r"(a) : "l"(p));
    return a;
}
__device__ __forceinline__ uint32_t cvt_tf32(float v) {
    uint32_t r;
    asm("cvt.rna.tf32.f32 %0, %1;" : "=r"(r) : "f"(v));
    return r;
}
// hi via cvt.rna; lo passed as raw fp32 bits (HMMA truncates low mantissa)
__device__ __forceinline__ void split2(float v, uint32_t& hi, uint32_t& lo) {
    hi = cvt_tf32(v);
    lo = __float_as_uint(v - __uint_as_float(hi));
}
// D += A*B, m16n8k8 tf32
__device__ __forceinline__ void mma8(float* c,
                                     uint32_t a0, uint32_t a1, uint32_t a2, uint32_t a3,
                                     uint32_t b0, uint32_t b1) {
    asm volatile(
        "mma.sync.aligned.m16n8k8.row.col.f32.tf32.tf32.f32 "
        "{%0,%1,%2,%3}, {%4,%5,%6,%7}, {%8,%9}, {%0,%1,%2,%3};"
        : "+f"(c[0]), "+f"(c[1]), "+f"(c[2]), "+f"(c[3])
        : "r"(a0), "r"(a1), "r"(a2), "r"(a3), "r"(b0), "r"(b1));
}
__device__ __forceinline__ void cp16(uint32_t saddr, const void* gptr) {
    asm volatile("cp.async.cg.shared.global [%0], [%1], 16;"
                 :: "r"(saddr), "l"(gptr) : "memory");
}
#define CP_COMMIT() asm volatile("cp.async.commit_group;" ::: "memory")
#define CP_WAIT(n)  asm volatile("cp.async.wait_group %0;" :: "n"(n) : "memory")

// ---------------------------------------------------------------------------
// Weight transposes (once per launch)
// ---------------------------------------------------------------------------
__global__ void transpose_qkv(const float* __restrict__ Wq,
                              const float* __restrict__ Wk,
                              const float* __restrict__ Wv)
{
    __shared__ float t[32][33];
    const int z = blockIdx.z >> 4;
    const int h = blockIdx.z & 15;
    const float* in = (z == 0 ? Wq : z == 1 ? Wk : Wv) + (size_t)h * D_ * DK_;
    const int j0 = blockIdx.x * 32;
    const int d0 = blockIdx.y * 32;
    const int tx = threadIdx.x, ty = threadIdx.y;
#pragma unroll
    for (int q = 0; q < 4; q++)
        t[ty + 8 * q][tx] = in[(size_t)(d0 + ty + 8 * q) * DK_ + j0 + tx];
    __syncthreads();
    float* outp = g_WT + (size_t)z * D_ * D_ + (size_t)(h * 64 + j0) * D_ + d0;
#pragma unroll
    for (int q = 0; q < 4; q++)
        outp[(size_t)(ty + 8 * q) * D_ + tx] = t[tx][ty + 8 * q];
}

__global__ void transpose_wo(const float* __restrict__ Wo)
{
    __shared__ float t[32][33];
    const int n0 = blockIdx.x * 32;
    const int j0 = blockIdx.y * 32;
    const int tx = threadIdx.x, ty = threadIdx.y;
#pragma unroll
    for (int q = 0; q < 4; q++)
        t[ty + 8 * q][tx] = Wo[(size_t)(j0 + ty + 8 * q) * D_ + n0 + tx];
    __syncthreads();
#pragma unroll
    for (int q = 0; q < 4; q++)
        g_WoT[(size_t)(n0 + ty + 8 * q) * D_ + j0 + tx] = t[tx][ty + 8 * q];
}

// ---------------------------------------------------------------------------
// GEMM: 128x128x32 CTA tile, 4 warps (2x2), warp tile 64x64, cp.async 2-stage.
// 128 threads -> 2 CTAs/SM.  (unchanged, proven in R8)
// ---------------------------------------------------------------------------
#define GPAD 36
#define GEMM_SMEM (2 * 2 * 128 * GPAD * 4)   // 73728 B

__device__ __forceinline__ void gemm_chunk4(const float (*As)[GPAD],
                                            const float (*Bs)[GPAD],
                                            int wm, int wn, int g, int t,
                                            float c[4][8][4])
{
#pragma unroll
    for (int ks = 0; ks < 4; ks++) {
        const int kc = ks * 8;
        uint32_t ah[4][4], al[4][4];
#pragma unroll
        for (int mf = 0; mf < 4; mf++) {
            const int r = wm * 64 + mf * 16;
            split2(As[r + g][kc + t],          ah[mf][0], al[mf][0]);
            split2(As[r + g + 8][kc + t],      ah[mf][1], al[mf][1]);
            split2(As[r + g][kc + t + 4],      ah[mf][2], al[mf][2]);
            split2(As[r + g + 8][kc + t + 4],  ah[mf][3], al[mf][3]);
        }
#pragma unroll
        for (int nf = 0; nf < 8; nf++) {
            const int n = wn * 64 + nf * 8;
            uint32_t bh0, bl0, bh1, bl1;
            split2(Bs[n + g][kc + t],     bh0, bl0);
            split2(Bs[n + g][kc + t + 4], bh1, bl1);
#pragma unroll
            for (int mf = 0; mf < 4; mf++) {
                mma8(c[mf][nf], ah[mf][0], ah[mf][1], ah[mf][2], ah[mf][3], bh0, bh1);
                mma8(c[mf][nf], ah[mf][0], ah[mf][1], ah[mf][2], ah[mf][3], bl0, bl1);
                mma8(c[mf][nf], al[mf][0], al[mf][1], al[mf][2], al[mf][3], bh0, bh1);
            }
        }
    }
}

// ---------------------------------------------------------------------------
// QKV projection
// ---------------------------------------------------------------------------
__global__ __launch_bounds__(128, 2) void qkv_mma(
    const float* __restrict__ x,
    const float* __restrict__ bq, const float* __restrict__ bk,
    const float* __restrict__ bv)
{
    extern __shared__ float sm[];
    float (*Asm)[GPAD] = (float(*)[GPAD])sm;
    float (*Bsm)[GPAD] = (float(*)[GPAD])(sm + 2 * 128 * GPAD);

    const int tid = threadIdx.x;
    const int wid = tid >> 5;
    const int lane = tid & 31;
    const int g = lane >> 2, t = lane & 3;
    const int wm = wid >> 1, wn = wid & 1;
    const int m0 = blockIdx.x * 128;
    const int n0 = blockIdx.y * 128;
    const int z  = blockIdx.z;

    const float* Bt = g_WT + (size_t)z * D_ * D_;
    float* outp = (z == 0) ? g_Q : (z == 1) ? g_K : g_V;
    const float* bias = (z == 0) ? bq : (z == 1) ? bk : bv;

    const int lr = tid >> 3;          // 0..15 (x8 -> 128 rows)
    const int lc = (tid & 7) * 4;

    const uint32_t aB = smem_u32(sm);
    const uint32_t bB = aB + 2 * 128 * GPAD * 4;

#pragma unroll
    for (int i = 0; i < 8; i++) {
        const int r = lr + i * 16;
        cp16(aB + (uint32_t)(r * GPAD + lc) * 4, &x [(size_t)(m0 + r) * D_ + lc]);
        cp16(bB + (uint32_t)(r * GPAD + lc) * 4, &Bt[(size_t)(n0 + r) * D_ + lc]);
    }
    CP_COMMIT();

    float c[4][8][4];
#pragma unroll
    for (int a = 0; a < 4; a++)
#pragma unroll
        for (int b = 0; b < 8; b++)
#pragma unroll
            for (int q = 0; q < 4; q++) c[a][b][q] = 0.0f;

    for (int ch = 0; ch < 32; ch++) {
        const int s = ch & 1;
        if (ch + 1 < 32) {
            const int k0 = (ch + 1) * 32;
            const uint32_t so = (uint32_t)((ch + 1) & 1) * 128 * GPAD * 4;
#pragma unroll
            for (int i = 0; i < 8; i++) {
                const int r = lr + i * 16;
                cp16(aB + so + (uint32_t)(r * GPAD + lc) * 4,
                     &x [(size_t)(m0 + r) * D_ + k0 + lc]);
                cp16(bB + so + (uint32_t)(r * GPAD + lc) * 4,
                     &Bt[(size_t)(n0 + r) * D_ + k0 + lc]);
            }
            CP_COMMIT();
            CP_WAIT(1);
        } else {
            CP_WAIT(0);
        }
        __syncthreads();
        gemm_chunk4(&Asm[s * 128], &Bsm[s * 128], wm, wn, g, t, c);
        __syncthreads();
    }

#pragma unroll
    for (int mf = 0; mf < 4; mf++) {
#pragma unroll
        for (int nf = 0; nf < 8; nf++) {
            const int j = n0 + wn * 64 + nf * 8 + 2 * t;
            const int head = j >> 6, kin = j & 63;
            const float bz0 = bias[j], bz1 = bias[j + 1];
#pragma unroll
            for (int rr = 0; rr < 2; rr++) {
                const int m = m0 + wm * 64 + mf * 16 + g + rr * 8;
                const int b = m >> 11, sidx = m & 2047;
                float* p = outp + ((size_t)(b * H_ + head) * S_ + sidx) * DK_ + kin;
                *(float2*)p = make_float2(c[mf][nf][rr * 2] + bz0,
                                          c[mf][nf][rr * 2 + 1] + bz1);
            }
        }
    }
}

// ---------------------------------------------------------------------------
// Output projection
// ---------------------------------------------------------------------------
__global__ __launch_bounds__(128, 2) void out_mma(
    const float* __restrict__ bo, float* __restrict__ out)
{
    extern __shared__ float sm[];
    float (*Asm)[GPAD] = (float(*)[GPAD])sm;
    float (*Bsm)[GPAD] = (float(*)[GPAD])(sm + 2 * 128 * GPAD);

    const int tid = threadIdx.x;
    const int wid = tid >> 5;
    const int lane = tid & 31;
    const int g = lane >> 2, t = lane & 3;
    const int wm = wid >> 1, wn = wid & 1;
    const int m0 = blockIdx.x * 128;
    const int n0 = blockIdx.y * 128;
    const int bb = m0 >> 11;
    const int sbase = m0 & 2047;

    const int lr = tid >> 3;
    const int lc = (tid & 7) * 4;

    const uint32_t aB = smem_u32(sm);
    const uint32_t bB = aB + 2 * 128 * GPAD * 4;

#pragma unroll
    for (int i = 0; i < 8; i++) {
        const int r = lr + i * 16;
        const float* src = g_O + ((size_t)(bb * H_) * S_ + sbase + r) * DK_ + lc;
        cp16(aB + (uint32_t)(r * GPAD + lc) * 4, src);
        cp16(bB + (uint32_t)(r * GPAD + lc) * 4, &g_WoT[(size_t)(n0 + r) * D_ + lc]);
    }
    CP_COMMIT();

    float c[4][8][4];
#pragma unroll
    for (int a = 0; a < 4; a++)
#pragma unroll
        for (int b = 0; b < 8; b++)
#pragma unroll
            for (int q = 0; q < 4; q++) c[a][b][q] = 0.0f;

    for (int ch = 0; ch < 32; ch++) {
        const int s = ch & 1;
        if (ch + 1 < 32) {
            const int k0 = (ch + 1) * 32;
            const int head = k0 >> 6, kin = k0 & 63;
            const uint32_t so = (uint32_t)((ch + 1) & 1) * 128 * GPAD * 4;
#pragma unroll
            for (int i = 0; i < 8; i++) {
                const int r = lr + i * 16;
                const float* src = g_O +
                    ((size_t)(bb * H_ + head) * S_ + sbase + r) * DK_ + kin + lc;
                cp16(aB + so + (uint32_t)(r * GPAD + lc) * 4, src);
                cp16(bB + so + (uint32_t)(r * GPAD + lc) * 4,
                     &g_WoT[(size_t)(n0 + r) * D_ + k0 + lc]);
            }
            CP_COMMIT();
            CP_WAIT(1);
        } else {
            CP_WAIT(0);
        }
        __syncthreads();
        gemm_chunk4(&Asm[s * 128], &Bsm[s * 128], wm, wn, g, t, c);
        __syncthreads();
    }

#pragma unroll
    for (int mf = 0; mf < 4; mf++) {
#pragma unroll
        for (int nf = 0; nf < 8; nf++) {
            const int j = n0 + wn * 64 + nf * 8 + 2 * t;
            const float bz0 = bo[j], bz1 = bo[j + 1];
#pragma unroll
            for (int rr = 0; rr < 2; rr++) {
                const int m = m0 + wm * 64 + mf * 16 + g + rr * 8;
                *(float2*)&out[(size_t)m * D_ + j] =
                    make_float2(c[mf][nf][rr * 2] + bz0, c[mf][nf][rr * 2 + 1] + bz1);
            }
        }
    }
}

// ---------------------------------------------------------------------------
// Causal flash attention v4: R4 structure + interleaved {hi,lo} float2 packing.
//   256 threads (8 warps), q-tile 128 (16 rows/warp), kv-tile 64.
//   QP [q][d] packed (pre-split once). PP [q][kv] packed (split in softmax).
//   KP [kv][d] packed; VP [d][kv] packed (transposed = conflict-free B reads).
//   All MMA-phase accesses are single LDS.64, bank-conflict-free.
// ---------------------------------------------------------------------------
#define APAD 68
#define ATTN_SMEM ((128 + 128 + 64 + 64) * APAD * 8)   // 208896 B

__global__ __launch_bounds__(256) void attn_pk()
{
    extern __shared__ float2 smp[];
    float2 (*QP)[APAD] = (float2(*)[APAD])smp;     // [128] packed Q {hi,lo}
    float2 (*PP)[APAD] = QP + 128;                 // [128] packed P
    float2 (*KP)[APAD] = PP + 128;                 // [64]  packed K  [kv][d]
    float2 (*VP)[APAD] = KP + 64;                  // [64]  packed V^T [d][kv]

    const int qb = (int)(gridDim.x - 1) - (int)blockIdx.x;   // big tiles first
    const int bh = blockIdx.y;
    const float* Qp = g_Q + (size_t)bh * S_ * DK_;
    const float* Kp = g_K + (size_t)bh * S_ * DK_;
    const float* Vp = g_V + (size_t)bh * S_ * DK_;
    float*       Op = g_O + (size_t)bh * S_ * DK_;

    const int tid = threadIdx.x;
    const int wid = tid >> 5;
    const int lane = tid & 31;
    const int g = lane >> 2, t = lane & 3;
    const int wrow = wid * 16;          // warp's row base within the 128-tile
    const int q0 = qb * 128;

    // ---- stage Q: load, scale by 1/8, split, store packed ----
    {
        const int r = tid >> 1;
        const int c0 = (tid & 1) * 32;
#pragma unroll
        for (int i = 0; i < 8; i++) {
            const int c = c0 + 4 * i;
            float4 q = *(const float4*)&Qp[(size_t)(q0 + r) * DK_ + c];
            uint32_t hx, lx, hy, ly, hz, lz, hw, lw;
            split2(q.x * 0.125f, hx, lx); split2(q.y * 0.125f, hy, ly);
            split2(q.z * 0.125f, hz, lz); split2(q.w * 0.125f, hw, lw);
            *(float4*)&QP[r][c] =
                make_float4(__uint_as_float(hx), __uint_as_float(lx),
                            __uint_as_float(hy), __uint_as_float(ly));
            *(float4*)&QP[r][c + 2] =
                make_float4(__uint_as_float(hz), __uint_as_float(lz),
                            __uint_as_float(hw), __uint_as_float(lw));
        }
    }

    float cO[8][4];
#pragma unroll
    for (int nf = 0; nf < 8; nf++)
#pragma unroll
        for (int q = 0; q < 4; q++) cO[nf][q] = 0.0f;
    float m0v = -1e30f, m1v = -1e30f, l0 = 0.0f, l1 = 0.0f;

    const int ntiles = 2 * qb + 2;

    // prefetch mappings (R4-proven: coalesced loads)
    const int krow = tid >> 4;            // 0..15 (+16p)
    const int kcol = (tid & 15) * 4;      // 0..60
    const int vc   = tid & 63;            // kv column
    const int vq   = tid >> 6;            // 0..3 -> d-base vq*16

    float4 kreg[4], vreg[4];
#pragma unroll
    for (int p = 0; p < 4; p++) {
        kreg[p] = *(const float4*)&Kp[(size_t)(krow + 16 * p) * DK_ + kcol];
        vreg[p] = *(const float4*)&Vp[(size_t)vc * DK_ + vq * 16 + 4 * p];
    }

    for (int kt = 0; kt < ntiles; kt++) {
        const int kv0 = kt * 64;
        __syncthreads();   // previous compute done reading K/V smem

        // ---- cooperative split & packed store (K direct, V transposed) ----
#pragma unroll
        for (int p = 0; p < 4; p++) {
            {
                float4 k4 = kreg[p];
                uint32_t hx, lx, hy, ly, hz, lz, hw, lw;
                split2(k4.x, hx, lx); split2(k4.y, hy, ly);
                split2(k4.z, hz, lz); split2(k4.w, hw, lw);
                *(float4*)&KP[krow + 16 * p][kcol] =
                    make_float4(__uint_as_float(hx), __uint_as_float(lx),
                                __uint_as_float(hy), __uint_as_float(ly));
                *(float4*)&KP[krow + 16 * p][kcol + 2] =
                    make_float4(__uint_as_float(hz), __uint_as_float(lz),
                                __uint_as_float(hw), __uint_as_float(lw));
            }
            {
                float4 v4 = vreg[p];
                uint32_t ax, lx, ay, ly, az, lz, aw, lw;
                split2(v4.x, ax, lx); split2(v4.y, ay, ly);
                split2(v4.z, az, lz); split2(v4.w, aw, lw);
                const int d0 = vq * 16 + 4 * p;
                VP[d0 + 0][vc] = make_float2(__uint_as_float(ax), __uint_as_float(lx));
                VP[d0 + 1][vc] = make_float2(__uint_as_float(ay), __uint_as_float(ly));
                VP[d0 + 2][vc] = make_float2(__uint_as_float(az), __uint_as_float(lz));
                VP[d0 + 3][vc] = make_float2(__uint_as_float(aw), __uint_as_float(lw));
            }
        }
        __syncthreads();   // tiles (and, at kt=0, QP) ready

        // ---- prefetch next tile into registers (overlaps compute) ----
        if (kt + 1 < ntiles) {
            const int nk = kv0 + 64;
#pragma unroll
            for (int p = 0; p < 4; p++) {
                kreg[p] = *(const float4*)&Kp[(size_t)(nk + krow + 16 * p) * DK_ + kcol];
                vreg[p] = *(const float4*)&Vp[(size_t)(nk + vc) * DK_ + vq * 16 + 4 * p];
            }
        }

        // warps beyond their causal diagonal skip compute (barriers already passed)
        if (kv0 > q0 + wrow + 15) continue;

        // ---- S = Q K^T (tf32 x3); all operands 1 LDS.64 each ----
        float cS[8][4];
#pragma unroll
        for (int nf = 0; nf < 8; nf++)
#pragma unroll
            for (int q = 0; q < 4; q++) cS[nf][q] = 0.0f;

#pragma unroll
        for (int ks = 0; ks < 8; ks++) {
            const int kc = ks * 8;
            const float2 a0 = QP[wrow + g][kc + t];
            const float2 a1 = QP[wrow + g + 8][kc + t];
            const float2 a2 = QP[wrow + g][kc + t + 4];
            const float2 a3 = QP[wrow + g + 8][kc + t + 4];
            const uint32_t ah0 = __float_as_uint(a0.x), al0 = __float_as_uint(a0.y);
            const uint32_t ah1 = __float_as_uint(a1.x), al1 = __float_as_uint(a1.y);
            const uint32_t ah2 = __float_as_uint(a2.x), al2 = __float_as_uint(a2.y);
            const uint32_t ah3 = __float_as_uint(a3.x), al3 = __float_as_uint(a3.y);
#pragma unroll
            for (int nf = 0; nf < 8; nf++) {
                const float2 b0 = KP[nf * 8 + g][kc + t];
                const float2 b1 = KP[nf * 8 + g][kc + t + 4];
                const uint32_t bh0 = __float_as_uint(b0.x), bl0 = __float_as_uint(b0.y);
                const uint32_t bh1 = __float_as_uint(b1.x), bl1 = __float_as_uint(b1.y);
                mma8(cS[nf], ah0, ah1, ah2, ah3, bh0, bh1);
                mma8(cS[nf], ah0, ah1, ah2, ah3, bl0, bl1);
                mma8(cS[nf], al0, al1, al2, al3, bh0, bh1);
            }
        }

        // ---- causal mask (only tiles crossing this warp's diagonal) ----
        if (kv0 + 63 > q0 + wrow) {
            const int r0g = q0 + wrow + g;
            const int r1g = r0g + 8;
#pragma unroll
            for (int nf = 0; nf < 8; nf++) {
                const int col = kv0 + nf * 8 + 2 * t;
                if (col     > r0g) cS[nf][0] = -1e30f;
                if (col + 1 > r0g) cS[nf][1] = -1e30f;
                if (col     > r1g) cS[nf][2] = -1e30f;
                if (col + 1 > r1g) cS[nf][3] = -1e30f;
            }
        }

        // ---- online softmax (rows wrow+g, wrow+g+8; quad reduction) ----
        float mx0 = -1e30f, mx1 = -1e30f;
#pragma unroll
        for (int nf = 0; nf < 8; nf++) {
            mx0 = fmaxf(mx0, fmaxf(cS[nf][0], cS[nf][1]));
            mx1 = fmaxf(mx1, fmaxf(cS[nf][2], cS[nf][3]));
        }
        mx0 = fmaxf(mx0, __shfl_xor_sync(0xffffffffu, mx0, 1));
        mx0 = fmaxf(mx0, __shfl_xor_sync(0xffffffffu, mx0, 2));
        mx1 = fmaxf(mx1, __shfl_xor_sync(0xffffffffu, mx1, 1));
        mx1 = fmaxf(mx1, __shfl_xor_sync(0xffffffffu, mx1, 2));
        const float mn0 = fmaxf(m0v, mx0), mn1 = fmaxf(m1v, mx1);
        const float corr0 = __expf(m0v - mn0), corr1 = __expf(m1v - mn1);
        float rs0 = 0.0f, rs1 = 0.0f;
#pragma unroll
        for (int nf = 0; nf < 8; nf++) {
            const float p0 = __expf(cS[nf][0] - mn0);
            const float p1 = __expf(cS[nf][1] - mn0);
            const float p2 = __expf(cS[nf][2] - mn1);
            const float p3 = __expf(cS[nf][3] - mn1);
            rs0 += p0 + p1; rs1 += p2 + p3;
            uint32_t h0, lo0, h1, lo1;
            split2(p0, h0, lo0); split2(p1, h1, lo1);
            *(float4*)&PP[wrow + g][nf * 8 + 2 * t] =
                make_float4(__uint_as_float(h0), __uint_as_float(lo0),
                            __uint_as_float(h1), __uint_as_float(lo1));
            split2(p2, h0, lo0); split2(p3, h1, lo1);
            *(float4*)&PP[wrow + g + 8][nf * 8 + 2 * t] =
                make_float4(__uint_as_float(h0), __uint_as_float(lo0),
                            __uint_as_float(h1), __uint_as_float(lo1));
        }
        rs0 += __shfl_xor_sync(0xffffffffu, rs0, 1);
        rs0 += __shfl_xor_sync(0xffffffffu, rs0, 2);
        rs1 += __shfl_xor_sync(0xffffffffu, rs1, 1);
        rs1 += __shfl_xor_sync(0xffffffffu, rs1, 2);
        l0 = l0 * corr0 + rs0; l1 = l1 * corr1 + rs1;
        m0v = mn0; m1v = mn1;
#pragma unroll
        for (int nf = 0; nf < 8; nf++) {
            cO[nf][0] *= corr0; cO[nf][1] *= corr0;
            cO[nf][2] *= corr1; cO[nf][3] *= corr1;
        }
        __syncwarp();   // P rows visible within the owning warp

        // ---- O += P V (tf32 x3); all operands 1 LDS.64 each ----
#pragma unroll
        for (int ks = 0; ks < 8; ks++) {
            const int kc = ks * 8;
            const float2 a0 = PP[wrow + g][kc + t];
            const float2 a1 = PP[wrow + g + 8][kc + t];
            const float2 a2 = PP[wrow + g][kc + t + 4];
            const float2 a3 = PP[wrow + g + 8][kc + t + 4];
            const uint32_t ah0 = __float_as_uint(a0.x), al0 = __float_as_uint(a0.y);
            const uint32_t ah1 = __float_as_uint(a1.x), al1 = __float_as_uint(a1.y);
            const uint32_t ah2 = __float_as_uint(a2.x), al2 = __float_as_uint(a2.y);
            const uint32_t ah3 = __float_as_uint(a3.x), al3 = __float_as_uint(a3.y);
#pragma unroll
            for (int nf = 0; nf < 8; nf++) {
                const float2 b0 = VP[nf * 8 + g][kc + t];
                const float2 b1 = VP[nf * 8 + g][kc + t + 4];
                const uint32_t bh0 = __float_as_uint(b0.x), bl0 = __float_as_uint(b0.y);
                const uint32_t bh1 = __float_as_uint(b1.x), bl1 = __float_as_uint(b1.y);
                mma8(cO[nf], ah0, ah1, ah2, ah3, bh0, bh1);
                mma8(cO[nf], ah0, ah1, ah2, ah3, bl0, bl1);
                mma8(cO[nf], al0, al1, al2, al3, bh0, bh1);
            }
        }
    }

    // ---- normalize + store O ----
    const float inv0 = 1.0f / l0, inv1 = 1.0f / l1;
#pragma unroll
    for (int nf = 0; nf < 8; nf++) {
        const int col = nf * 8 + 2 * t;
        *(float2*)&Op[(size_t)(q0 + wrow + g) * DK_ + col] =
            make_float2(cO[nf][0] * inv0, cO[nf][1] * inv0);
        *(float2*)&Op[(size_t)(q0 + wrow + g + 8) * DK_ + col] =
            make_float2(cO[nf][2] * inv1, cO[nf][3] * inv1);
    }
}

// ---------------------------------------------------------------------------
extern "C" void kernel_launch(void* const* d_in, const int* in_sizes, int n_in,
                              void* d_out, int out_size)
{
    const float* x  = (const float*)d_in[0];
    const float* Wq = (const float*)d_in[2];
    const float* bq = (const float*)d_in[3];
    const float* Wk = (const float*)d_in[4];
    const float* bk = (const float*)d_in[5];
    const float* Wv = (const float*)d_in[6];
    const float* bv = (const float*)d_in[7];
    const float* Wo = (const float*)d_in[8];
    const float* bo = (const float*)d_in[9];
    float* out = (float*)d_out;

    cudaFuncSetAttribute(qkv_mma, cudaFuncAttributeMaxDynamicSharedMemorySize, GEMM_SMEM);
    cudaFuncSetAttribute(out_mma, cudaFuncAttributeMaxDynamicSharedMemorySize, GEMM_SMEM);
    cudaFuncSetAttribute(attn_pk, cudaFuncAttributeMaxDynamicSharedMemorySize, ATTN_SMEM);

    transpose_qkv<<<dim3(2, 32, 48), dim3(32, 8)>>>(Wq, Wk, Wv);
    transpose_wo<<<dim3(32, 32), dim3(32, 8)>>>(Wo);

    qkv_mma<<<dim3(M_ / 128, D_ / 128, 3), 128, GEMM_SMEM>>>(x, bq, bk, bv);

    attn_pk<<<dim3(S_ / 128, B_ * H_), 256, ATTN_SMEM>>>();

    out_mma<<<dim3(M_ / 128, D_ / 128), 128, GEMM_SMEM>>>(bo, out);
}

// round 12
// speedup vs baseline: 1.1047x; 1.1047x over previous
#include <cuda_runtime.h>
#include <cstdint>

#define B_  4
#define S_  2048
#define D_  1024
#define H_  16
#define DK_ 64
#define M_  (B_ * S_)                    // 8192
#define QKV_ELEMS (B_ * H_ * S_ * DK_)   // 8388608

// Scratch (device globals; no runtime allocation)
__device__ float g_Q[QKV_ELEMS];
__device__ float g_K[QKV_ELEMS];
__device__ float g_V[QKV_ELEMS];
__device__ float g_O[QKV_ELEMS];
__device__ float g_WThi[3 * D_ * D_];    // tf32-hi of W^T for Q,K,V: [z][j][d]
__device__ float g_WTlo[3 * D_ * D_];    // residual lo
__device__ float g_WoThi[D_ * D_];       // tf32-hi of Wo^T: [n][j]
__device__ float g_WoTlo[D_ * D_];

// ---------------------------------------------------------------------------
// Helpers (base-ISA only: mma.sync + cp.async)
// ---------------------------------------------------------------------------
__device__ __forceinline__ uint32_t smem_u32(const void* p) {
    uint32_t a;
    asm("{ .reg .u64 t; cvta.to.shared.u64 t, %1; cvt.u32.u64 %0, t; }"
        : "=r"(a) : "l"(p));
    return a;
}
__device__ __forceinline__ uint32_t cvt_tf32(float v) {
    uint32_t r;
    asm("cvt.rna.tf32.f32 %0, %1;" : "=r"(r) : "f"(v));
    return r;
}
// hi via cvt.rna; lo passed as raw fp32 bits (HMMA truncates low mantissa)
__device__ __forceinline__ void split2(float v, uint32_t& hi, uint32_t& lo) {
    hi = cvt_tf32(v);
    lo = __float_as_uint(v - __uint_as_float(hi));
}
// D += A*B, m16n8k8 tf32
__device__ __forceinline__ void mma8(float* c,
                                     uint32_t a0, uint32_t a1, uint32_t a2, uint32_t a3,
                                     uint32_t b0, uint32_t b1) {
    asm volatile(
        "mma.sync.aligned.m16n8k8.row.col.f32.tf32.tf32.f32 "
        "{%0,%1,%2,%3}, {%4,%5,%6,%7}, {%8,%9}, {%0,%1,%2,%3};"
        : "+f"(c[0]), "+f"(c[1]), "+f"(c[2]), "+f"(c[3])
        : "r"(a0), "r"(a1), "r"(a2), "r"(a3), "r"(b0), "r"(b1));
}
__device__ __forceinline__ void cp16(uint32_t saddr, const void* gptr) {
    asm volatile("cp.async.cg.shared.global [%0], [%1], 16;"
                 :: "r"(saddr), "l"(gptr) : "memory");
}
#define CP_COMMIT() asm volatile("cp.async.commit_group;" ::: "memory")
#define CP_WAIT(n)  asm volatile("cp.async.wait_group %0;" :: "n"(n) : "memory")

// ---------------------------------------------------------------------------
// Weight transposes + tf32 hi/lo pre-split (once per launch)
// ---------------------------------------------------------------------------
__global__ void transpose_qkv(const float* __restrict__ Wq,
                              const float* __restrict__ Wk,
                              const float* __restrict__ Wv)
{
    __shared__ float t[32][33];
    const int z = blockIdx.z >> 4;
    const int h = blockIdx.z & 15;
    const float* in = (z == 0 ? Wq : z == 1 ? Wk : Wv) + (size_t)h * D_ * DK_;
    const int j0 = blockIdx.x * 32;
    const int d0 = blockIdx.y * 32;
    const int tx = threadIdx.x, ty = threadIdx.y;
#pragma unroll
    for (int q = 0; q < 4; q++)
        t[ty + 8 * q][tx] = in[(size_t)(d0 + ty + 8 * q) * DK_ + j0 + tx];
    __syncthreads();
    const size_t ob = (size_t)z * D_ * D_ + (size_t)(h * 64 + j0) * D_ + d0;
#pragma unroll
    for (int q = 0; q < 4; q++) {
        const float v = t[tx][ty + 8 * q];
        const uint32_t hi = cvt_tf32(v);
        g_WThi[ob + (size_t)(ty + 8 * q) * D_ + tx] = __uint_as_float(hi);
        g_WTlo[ob + (size_t)(ty + 8 * q) * D_ + tx] = v - __uint_as_float(hi);
    }
}

__global__ void transpose_wo(const float* __restrict__ Wo)
{
    __shared__ float t[32][33];
    const int n0 = blockIdx.x * 32;
    const int j0 = blockIdx.y * 32;
    const int tx = threadIdx.x, ty = threadIdx.y;
#pragma unroll
    for (int q = 0; q < 4; q++)
        t[ty + 8 * q][tx] = Wo[(size_t)(j0 + ty + 8 * q) * D_ + n0 + tx];
    __syncthreads();
#pragma unroll
    for (int q = 0; q < 4; q++) {
        const float v = t[tx][ty + 8 * q];
        const uint32_t hi = cvt_tf32(v);
        g_WoThi[(size_t)(n0 + ty + 8 * q) * D_ + j0 + tx] = __uint_as_float(hi);
        g_WoTlo[(size_t)(n0 + ty + 8 * q) * D_ + j0 + tx] = v - __uint_as_float(hi);
    }
}

// ---------------------------------------------------------------------------
// GEMM: 128x128x32 CTA tile, 4 warps (2x2), warp tile 64x64, cp.async 2-stage.
// B operand pre-split: smem holds A (fp32) + Bhi + Blo planes. 2 CTAs/SM.
// ---------------------------------------------------------------------------
#define GPAD 36
#define GEMM_SMEM (2 * 3 * 128 * GPAD * 4)   // 110592 B

__device__ __forceinline__ void gemm_chunk4(const float (*As)[GPAD],
                                            const float (*Bhs)[GPAD],
                                            const float (*Bls)[GPAD],
                                            int wm, int wn, int g, int t,
                                            float c[4][8][4])
{
#pragma unroll
    for (int ks = 0; ks < 4; ks++) {
        const int kc = ks * 8;
        uint32_t ah[4][4], al[4][4];
#pragma unroll
        for (int mf = 0; mf < 4; mf++) {
            const int r = wm * 64 + mf * 16;
            split2(As[r + g][kc + t],          ah[mf][0], al[mf][0]);
            split2(As[r + g + 8][kc + t],      ah[mf][1], al[mf][1]);
            split2(As[r + g][kc + t + 4],      ah[mf][2], al[mf][2]);
            split2(As[r + g + 8][kc + t + 4],  ah[mf][3], al[mf][3]);
        }
#pragma unroll
        for (int nf = 0; nf < 8; nf++) {
            const int n = wn * 64 + nf * 8;
            const uint32_t bh0 = __float_as_uint(Bhs[n + g][kc + t]);
            const uint32_t bh1 = __float_as_uint(Bhs[n + g][kc + t + 4]);
            const uint32_t bl0 = __float_as_uint(Bls[n + g][kc + t]);
            const uint32_t bl1 = __float_as_uint(Bls[n + g][kc + t + 4]);
#pragma unroll
            for (int mf = 0; mf < 4; mf++) {
                mma8(c[mf][nf], ah[mf][0], ah[mf][1], ah[mf][2], ah[mf][3], bh0, bh1);
                mma8(c[mf][nf], ah[mf][0], ah[mf][1], ah[mf][2], ah[mf][3], bl0, bl1);
                mma8(c[mf][nf], al[mf][0], al[mf][1], al[mf][2], al[mf][3], bh0, bh1);
            }
        }
    }
}

// ---------------------------------------------------------------------------
// QKV projection
// ---------------------------------------------------------------------------
__global__ __launch_bounds__(128, 2) void qkv_mma(
    const float* __restrict__ x,
    const float* __restrict__ bq, const float* __restrict__ bk,
    const float* __restrict__ bv)
{
    extern __shared__ float sm[];
    float (*Asm)[GPAD]  = (float(*)[GPAD])sm;
    float (*Bhsm)[GPAD] = (float(*)[GPAD])(sm + 2 * 128 * GPAD);
    float (*Blsm)[GPAD] = (float(*)[GPAD])(sm + 4 * 128 * GPAD);

    const int tid = threadIdx.x;
    const int wid = tid >> 5;
    const int lane = tid & 31;
    const int g = lane >> 2, t = lane & 3;
    const int wm = wid >> 1, wn = wid & 1;
    const int m0 = blockIdx.x * 128;
    const int n0 = blockIdx.y * 128;
    const int z  = blockIdx.z;

    const float* Bth = g_WThi + (size_t)z * D_ * D_;
    const float* Btl = g_WTlo + (size_t)z * D_ * D_;
    float* outp = (z == 0) ? g_Q : (z == 1) ? g_K : g_V;
    const float* bias = (z == 0) ? bq : (z == 1) ? bk : bv;

    const int lr = tid >> 3;          // 0..15 (x8 -> 128 rows)
    const int lc = (tid & 7) * 4;

    const uint32_t aB  = smem_u32(sm);
    const uint32_t bhB = aB + 2 * 128 * GPAD * 4;
    const uint32_t blB = aB + 4 * 128 * GPAD * 4;

#pragma unroll
    for (int i = 0; i < 8; i++) {
        const int r = lr + i * 16;
        cp16(aB  + (uint32_t)(r * GPAD + lc) * 4, &x  [(size_t)(m0 + r) * D_ + lc]);
        cp16(bhB + (uint32_t)(r * GPAD + lc) * 4, &Bth[(size_t)(n0 + r) * D_ + lc]);
        cp16(blB + (uint32_t)(r * GPAD + lc) * 4, &Btl[(size_t)(n0 + r) * D_ + lc]);
    }
    CP_COMMIT();

    float c[4][8][4];
#pragma unroll
    for (int a = 0; a < 4; a++)
#pragma unroll
        for (int b = 0; b < 8; b++)
#pragma unroll
            for (int q = 0; q < 4; q++) c[a][b][q] = 0.0f;

    for (int ch = 0; ch < 32; ch++) {
        const int s = ch & 1;
        if (ch + 1 < 32) {
            const int k0 = (ch + 1) * 32;
            const uint32_t so = (uint32_t)((ch + 1) & 1) * 128 * GPAD * 4;
#pragma unroll
            for (int i = 0; i < 8; i++) {
                const int r = lr + i * 16;
                cp16(aB  + so + (uint32_t)(r * GPAD + lc) * 4,
                     &x  [(size_t)(m0 + r) * D_ + k0 + lc]);
                cp16(bhB + so + (uint32_t)(r * GPAD + lc) * 4,
                     &Bth[(size_t)(n0 + r) * D_ + k0 + lc]);
                cp16(blB + so + (uint32_t)(r * GPAD + lc) * 4,
                     &Btl[(size_t)(n0 + r) * D_ + k0 + lc]);
            }
            CP_COMMIT();
            CP_WAIT(1);
        } else {
            CP_WAIT(0);
        }
        __syncthreads();
        gemm_chunk4(&Asm[s * 128], &Bhsm[s * 128], &Blsm[s * 128], wm, wn, g, t, c);
        __syncthreads();
    }

#pragma unroll
    for (int mf = 0; mf < 4; mf++) {
#pragma unroll
        for (int nf = 0; nf < 8; nf++) {
            const int j = n0 + wn * 64 + nf * 8 + 2 * t;
            const int head = j >> 6, kin = j & 63;
            const float bz0 = bias[j], bz1 = bias[j + 1];
#pragma unroll
            for (int rr = 0; rr < 2; rr++) {
                const int m = m0 + wm * 64 + mf * 16 + g + rr * 8;
                const int b = m >> 11, sidx = m & 2047;
                float* p = outp + ((size_t)(b * H_ + head) * S_ + sidx) * DK_ + kin;
                *(float2*)p = make_float2(c[mf][nf][rr * 2] + bz0,
                                          c[mf][nf][rr * 2 + 1] + bz1);
            }
        }
    }
}

// ---------------------------------------------------------------------------
// Output projection
// ---------------------------------------------------------------------------
__global__ __launch_bounds__(128, 2) void out_mma(
    const float* __restrict__ bo, float* __restrict__ out)
{
    extern __shared__ float sm[];
    float (*Asm)[GPAD]  = (float(*)[GPAD])sm;
    float (*Bhsm)[GPAD] = (float(*)[GPAD])(sm + 2 * 128 * GPAD);
    float (*Blsm)[GPAD] = (float(*)[GPAD])(sm + 4 * 128 * GPAD);

    const int tid = threadIdx.x;
    const int wid = tid >> 5;
    const int lane = tid & 31;
    const int g = lane >> 2, t = lane & 3;
    const int wm = wid >> 1, wn = wid & 1;
    const int m0 = blockIdx.x * 128;
    const int n0 = blockIdx.y * 128;
    const int bb = m0 >> 11;
    const int sbase = m0 & 2047;

    const int lr = tid >> 3;
    const int lc = (tid & 7) * 4;

    const uint32_t aB  = smem_u32(sm);
    const uint32_t bhB = aB + 2 * 128 * GPAD * 4;
    const uint32_t blB = aB + 4 * 128 * GPAD * 4;

#pragma unroll
    for (int i = 0; i < 8; i++) {
        const int r = lr + i * 16;
        const float* src = g_O + ((size_t)(bb * H_) * S_ + sbase + r) * DK_ + lc;
        cp16(aB  + (uint32_t)(r * GPAD + lc) * 4, src);
        cp16(bhB + (uint32_t)(r * GPAD + lc) * 4, &g_WoThi[(size_t)(n0 + r) * D_ + lc]);
        cp16(blB + (uint32_t)(r * GPAD + lc) * 4, &g_WoTlo[(size_t)(n0 + r) * D_ + lc]);
    }
    CP_COMMIT();

    float c[4][8][4];
#pragma unroll
    for (int a = 0; a < 4; a++)
#pragma unroll
        for (int b = 0; b < 8; b++)
#pragma unroll
            for (int q = 0; q < 4; q++) c[a][b][q] = 0.0f;

    for (int ch = 0; ch < 32; ch++) {
        const int s = ch & 1;
        if (ch + 1 < 32) {
            const int k0 = (ch + 1) * 32;
            const int head = k0 >> 6, kin = k0 & 63;
            const uint32_t so = (uint32_t)((ch + 1) & 1) * 128 * GPAD * 4;
#pragma unroll
            for (int i = 0; i < 8; i++) {
                const int r = lr + i * 16;
                const float* src = g_O +
                    ((size_t)(bb * H_ + head) * S_ + sbase + r) * DK_ + kin + lc;
                cp16(aB  + so + (uint32_t)(r * GPAD + lc) * 4, src);
                cp16(bhB + so + (uint32_t)(r * GPAD + lc) * 4,
                     &g_WoThi[(size_t)(n0 + r) * D_ + k0 + lc]);
                cp16(blB + so + (uint32_t)(r * GPAD + lc) * 4,
                     &g_WoTlo[(size_t)(n0 + r) * D_ + k0 + lc]);
            }
            CP_COMMIT();
            CP_WAIT(1);
        } else {
            CP_WAIT(0);
        }
        __syncthreads();
        gemm_chunk4(&Asm[s * 128], &Bhsm[s * 128], &Blsm[s * 128], wm, wn, g, t, c);
        __syncthreads();
    }

#pragma unroll
    for (int mf = 0; mf < 4; mf++) {
#pragma unroll
        for (int nf = 0; nf < 8; nf++) {
            const int j = n0 + wn * 64 + nf * 8 + 2 * t;
            const float bz0 = bo[j], bz1 = bo[j + 1];
#pragma unroll
            for (int rr = 0; rr < 2; rr++) {
                const int m = m0 + wm * 64 + mf * 16 + g + rr * 8;
                *(float2*)&out[(size_t)m * D_ + j] =
                    make_float2(c[mf][nf][rr * 2] + bz0, c[mf][nf][rr * 2 + 1] + bz1);
            }
        }
    }
}

// ---------------------------------------------------------------------------
// Causal flash attention (R8 attn_mma2, proven 722us — UNCHANGED):
// 256 threads (8 warps), q-tile 128, kv-tile 64. K/V split hi/lo ONCE per tile
// (planar smem; V transposed [d][kv]). Register prefetch. Reversed qb order.
// ---------------------------------------------------------------------------
#define APAD 68
#define ATTN_SMEM ((2 * 128 + 4 * 64) * APAD * 4)   // 139264 B

__global__ __launch_bounds__(256) void attn_mma2()
{
    extern __shared__ float sm[];
    float (*Qs)[APAD]  = (float(*)[APAD])sm;     // [128][APAD] fp32 (scaled)
    float (*Ps)[APAD]  = Qs + 128;               // [128][APAD] fp32
    float (*Khi)[APAD] = Ps + 128;               // [64][APAD] tf32-hi bits
    float (*Klo)[APAD] = Khi + 64;               // [64][APAD] residual fp32
    float (*Vhi)[APAD] = Klo + 64;               // [64][APAD] transposed [d][kv]
    float (*Vlo)[APAD] = Vhi + 64;

    const int qb = (int)(gridDim.x - 1) - (int)blockIdx.x;   // big tiles first
    const int bh = blockIdx.y;
    const float* Qp = g_Q + (size_t)bh * S_ * DK_;
    const float* Kp = g_K + (size_t)bh * S_ * DK_;
    const float* Vp = g_V + (size_t)bh * S_ * DK_;
    float*       Op = g_O + (size_t)bh * S_ * DK_;

    const int tid = threadIdx.x;
    const int wid = tid >> 5;
    const int lane = tid & 31;
    const int g = lane >> 2, t = lane & 3;
    const int wrow = wid * 16;          // warp's row base within the 128-tile
    const int q0 = qb * 128;

    // ---- load Q (scaled by 1/8), 32 floats per thread ----
    {
        const int r = tid >> 1;
        const int c0 = (tid & 1) * 32;
#pragma unroll
        for (int i = 0; i < 8; i++) {
            float4 q = *(const float4*)&Qp[(size_t)(q0 + r) * DK_ + c0 + 4 * i];
            Qs[r][c0 + 4 * i + 0] = q.x * 0.125f;
            Qs[r][c0 + 4 * i + 1] = q.y * 0.125f;
            Qs[r][c0 + 4 * i + 2] = q.z * 0.125f;
            Qs[r][c0 + 4 * i + 3] = q.w * 0.125f;
        }
    }

    float cO[8][4];
#pragma unroll
    for (int nf = 0; nf < 8; nf++)
#pragma unroll
        for (int q = 0; q < 4; q++) cO[nf][q] = 0.0f;
    float m0v = -1e30f, m1v = -1e30f, l0 = 0.0f, l1 = 0.0f;

    const int ntiles = 2 * qb + 2;

    // prefetch mappings
    const int krow = tid >> 4;            // 0..15 (+16p)
    const int kcol = (tid & 15) * 4;      // 0..60
    const int vc   = tid & 63;            // kv column
    const int vq   = tid >> 6;            // 0..3 -> d-base vq*16

    float4 kreg[4], vreg[4];
#pragma unroll
    for (int p = 0; p < 4; p++) {
        kreg[p] = *(const float4*)&Kp[(size_t)(krow + 16 * p) * DK_ + kcol];
        vreg[p] = *(const float4*)&Vp[(size_t)vc * DK_ + vq * 16 + 4 * p];
    }

    for (int kt = 0; kt < ntiles; kt++) {
        const int kv0 = kt * 64;
        __syncthreads();   // previous compute done reading K/V smem

        // ---- cooperative split & store (K direct, V transposed) ----
#pragma unroll
        for (int p = 0; p < 4; p++) {
            float4 k4 = kreg[p];
            uint32_t hx = cvt_tf32(k4.x), hy = cvt_tf32(k4.y),
                     hz = cvt_tf32(k4.z), hw = cvt_tf32(k4.w);
            *(float4*)&Khi[krow + 16 * p][kcol] =
                make_float4(__uint_as_float(hx), __uint_as_float(hy),
                            __uint_as_float(hz), __uint_as_float(hw));
            *(float4*)&Klo[krow + 16 * p][kcol] =
                make_float4(k4.x - __uint_as_float(hx), k4.y - __uint_as_float(hy),
                            k4.z - __uint_as_float(hz), k4.w - __uint_as_float(hw));
            float4 v4 = vreg[p];
            uint32_t ax = cvt_tf32(v4.x), ay = cvt_tf32(v4.y),
                     az = cvt_tf32(v4.z), aw = cvt_tf32(v4.w);
            const int d0 = vq * 16 + 4 * p;
            Vhi[d0 + 0][vc] = __uint_as_float(ax);
            Vhi[d0 + 1][vc] = __uint_as_float(ay);
            Vhi[d0 + 2][vc] = __uint_as_float(az);
            Vhi[d0 + 3][vc] = __uint_as_float(aw);
            Vlo[d0 + 0][vc] = v4.x - __uint_as_float(ax);
            Vlo[d0 + 1][vc] = v4.y - __uint_as_float(ay);
            Vlo[d0 + 2][vc] = v4.z - __uint_as_float(az);
            Vlo[d0 + 3][vc] = v4.w - __uint_as_float(aw);
        }
        __syncthreads();   // tiles (and, at kt=0, Qs) ready

        // ---- prefetch next tile into registers (overlaps compute) ----
        if (kt + 1 < ntiles) {
            const int nk = kv0 + 64;
#pragma unroll
            for (int p = 0; p < 4; p++) {
                kreg[p] = *(const float4*)&Kp[(size_t)(nk + krow + 16 * p) * DK_ + kcol];
                vreg[p] = *(const float4*)&Vp[(size_t)(nk + vc) * DK_ + vq * 16 + 4 * p];
            }
        }

        // warps beyond their causal diagonal skip compute (barriers already passed)
        if (kv0 > q0 + wrow + 15) continue;

        // ---- S = Q K^T (tf32 x3) ----
        float cS[8][4];
#pragma unroll
        for (int nf = 0; nf < 8; nf++)
#pragma unroll
            for (int q = 0; q < 4; q++) cS[nf][q] = 0.0f;

#pragma unroll
        for (int ks = 0; ks < 8; ks++) {
            const int kc = ks * 8;
            uint32_t ah[4], al[4];
            split2(Qs[wrow + g][kc + t],         ah[0], al[0]);
            split2(Qs[wrow + g + 8][kc + t],     ah[1], al[1]);
            split2(Qs[wrow + g][kc + t + 4],     ah[2], al[2]);
            split2(Qs[wrow + g + 8][kc + t + 4], ah[3], al[3]);
#pragma unroll
            for (int nf = 0; nf < 8; nf++) {
                const uint32_t bh0 = __float_as_uint(Khi[nf * 8 + g][kc + t]);
                const uint32_t bh1 = __float_as_uint(Khi[nf * 8 + g][kc + t + 4]);
                const uint32_t bl0 = __float_as_uint(Klo[nf * 8 + g][kc + t]);
                const uint32_t bl1 = __float_as_uint(Klo[nf * 8 + g][kc + t + 4]);
                mma8(cS[nf], ah[0], ah[1], ah[2], ah[3], bh0, bh1);
                mma8(cS[nf], ah[0], ah[1], ah[2], ah[3], bl0, bl1);
                mma8(cS[nf], al[0], al[1], al[2], al[3], bh0, bh1);
            }
        }

        // ---- causal mask (only tiles crossing this warp's diagonal) ----
        if (kv0 + 63 > q0 + wrow) {
            const int r0g = q0 + wrow + g;
            const int r1g = r0g + 8;
#pragma unroll
            for (int nf = 0; nf < 8; nf++) {
                const int col = kv0 + nf * 8 + 2 * t;
                if (col     > r0g) cS[nf][0] = -1e30f;
                if (col + 1 > r0g) cS[nf][1] = -1e30f;
                if (col     > r1g) cS[nf][2] = -1e30f;
                if (col + 1 > r1g) cS[nf][3] = -1e30f;
            }
        }

        // ---- online softmax (rows wrow+g, wrow+g+8; quad reduction) ----
        float mx0 = -1e30f, mx1 = -1e30f;
#pragma unroll
        for (int nf = 0; nf < 8; nf++) {
            mx0 = fmaxf(mx0, fmaxf(cS[nf][0], cS[nf][1]));
            mx1 = fmaxf(mx1, fmaxf(cS[nf][2], cS[nf][3]));
        }
        mx0 = fmaxf(mx0, __shfl_xor_sync(0xffffffffu, mx0, 1));
        mx0 = fmaxf(mx0, __shfl_xor_sync(0xffffffffu, mx0, 2));
        mx1 = fmaxf(mx1, __shfl_xor_sync(0xffffffffu, mx1, 1));
        mx1 = fmaxf(mx1, __shfl_xor_sync(0xffffffffu, mx1, 2));
        const float mn0 = fmaxf(m0v, mx0), mn1 = fmaxf(m1v, mx1);
        const float corr0 = __expf(m0v - mn0), corr1 = __expf(m1v - mn1);
        float rs0 = 0.0f, rs1 = 0.0f;
#pragma unroll
        for (int nf = 0; nf < 8; nf++) {
            const float p0 = __expf(cS[nf][0] - mn0);
            const float p1 = __expf(cS[nf][1] - mn0);
            const float p2 = __expf(cS[nf][2] - mn1);
            const float p3 = __expf(cS[nf][3] - mn1);
            rs0 += p0 + p1; rs1 += p2 + p3;
            *(float2*)&Ps[wrow + g][nf * 8 + 2 * t]     = make_float2(p0, p1);
            *(float2*)&Ps[wrow + g + 8][nf * 8 + 2 * t] = make_float2(p2, p3);
        }
        rs0 += __shfl_xor_sync(0xffffffffu, rs0, 1);
        rs0 += __shfl_xor_sync(0xffffffffu, rs0, 2);
        rs1 += __shfl_xor_sync(0xffffffffu, rs1, 1);
        rs1 += __shfl_xor_sync(0xffffffffu, rs1, 2);
        l0 = l0 * corr0 + rs0; l1 = l1 * corr1 + rs1;
        m0v = mn0; m1v = mn1;
#pragma unroll
        for (int nf = 0; nf < 8; nf++) {
            cO[nf][0] *= corr0; cO[nf][1] *= corr0;
            cO[nf][2] *= corr1; cO[nf][3] *= corr1;
        }
        __syncwarp();   // P rows visible within the owning warp

        // ---- O += P V (tf32 x3) ----
#pragma unroll
        for (int ks = 0; ks < 8; ks++) {
            const int kc = ks * 8;
            uint32_t ah[4], al[4];
            split2(Ps[wrow + g][kc + t],         ah[0], al[0]);
            split2(Ps[wrow + g + 8][kc + t],     ah[1], al[1]);
            split2(Ps[wrow + g][kc + t + 4],     ah[2], al[2]);
            split2(Ps[wrow + g + 8][kc + t + 4], ah[3], al[3]);
#pragma unroll
            for (int nf = 0; nf < 8; nf++) {
                const uint32_t bh0 = __float_as_uint(Vhi[nf * 8 + g][kc + t]);
                const uint32_t bh1 = __float_as_uint(Vhi[nf * 8 + g][kc + t + 4]);
                const uint32_t bl0 = __float_as_uint(Vlo[nf * 8 + g][kc + t]);
                const uint32_t bl1 = __float_as_uint(Vlo[nf * 8 + g][kc + t + 4]);
                mma8(cO[nf], ah[0], ah[1], ah[2], ah[3], bh0, bh1);
                mma8(cO[nf], ah[0], ah[1], ah[2], ah[3], bl0, bl1);
                mma8(cO[nf], al[0], al[1], al[2], al[3], bh0, bh1);
            }
        }
    }

    // ---- normalize + store O ----
    const float inv0 = 1.0f / l0, inv1 = 1.0f / l1;
#pragma unroll
    for (int nf = 0; nf < 8; nf++) {
        const int col = nf * 8 + 2 * t;
        *(float2*)&Op[(size_t)(q0 + wrow + g) * DK_ + col] =
            make_float2(cO[nf][0] * inv0, cO[nf][1] * inv0);
        *(float2*)&Op[(size_t)(q0 + wrow + g + 8) * DK_ + col] =
            make_float2(cO[nf][2] * inv1, cO[nf][3] * inv1);
    }
}

// ---------------------------------------------------------------------------
extern "C" void kernel_launch(void* const* d_in, const int* in_sizes, int n_in,
                              void* d_out, int out_size)
{
    const float* x  = (const float*)d_in[0];
    const float* Wq = (const float*)d_in[2];
    const float* bq = (const float*)d_in[3];
    const float* Wk = (const float*)d_in[4];
    const float* bk = (const float*)d_in[5];
    const float* Wv = (const float*)d_in[6];
    const float* bv = (const float*)d_in[7];
    const float* Wo = (const float*)d_in[8];
    const float* bo = (const float*)d_in[9];
    float* out = (float*)d_out;

    cudaFuncSetAttribute(qkv_mma, cudaFuncAttributeMaxDynamicSharedMemorySize, GEMM_SMEM);
    cudaFuncSetAttribute(out_mma, cudaFuncAttributeMaxDynamicSharedMemorySize, GEMM_SMEM);
    cudaFuncSetAttribute(attn_mma2, cudaFuncAttributeMaxDynamicSharedMemorySize, ATTN_SMEM);

    transpose_qkv<<<dim3(2, 32, 48), dim3(32, 8)>>>(Wq, Wk, Wv);
    transpose_wo<<<dim3(32, 32), dim3(32, 8)>>>(Wo);

    qkv_mma<<<dim3(M_ / 128, D_ / 128, 3), 128, GEMM_SMEM>>>(x, bq, bk, bv);

    attn_mma2<<<dim3(S_ / 128, B_ * H_), 256, ATTN_SMEM>>>();

    out_mma<<<dim3(M_ / 128, D_ / 128), 128, GEMM_SMEM>>>(bo, out);
}

// round 13
// speedup vs baseline: 1.1275x; 1.0207x over previous
#include <cuda_runtime.h>
#include <cstdint>

#define B_  4
#define S_  2048
#define D_  1024
#define H_  16
#define DK_ 64
#define M_  (B_ * S_)                    // 8192
#define QKV_ELEMS (B_ * H_ * S_ * DK_)   // 8388608

// Scratch (device globals; no runtime allocation)
__device__ float g_Q[QKV_ELEMS];
__device__ float g_Khi[QKV_ELEMS];       // [bh][kv][d]  tf32-hi
__device__ float g_Klo[QKV_ELEMS];       // [bh][kv][d]  residual
__device__ float g_Vhi[QKV_ELEMS];       // [bh][d][kv]  (pre-transposed)
__device__ float g_Vlo[QKV_ELEMS];
__device__ float g_O[QKV_ELEMS];
__device__ float g_WThi[3 * D_ * D_];    // tf32-hi of W^T for Q,K,V: [z][j][d]
__device__ float g_WTlo[3 * D_ * D_];
__device__ float g_WoThi[D_ * D_];       // tf32-hi of Wo^T: [n][j]
__device__ float g_WoTlo[D_ * D_];

// ---------------------------------------------------------------------------
// Helpers (base-ISA only: mma.sync + cp.async)
// ---------------------------------------------------------------------------
__device__ __forceinline__ uint32_t smem_u32(const void* p) {
    uint32_t a;
    asm("{ .reg .u64 t; cvta.to.shared.u64 t, %1; cvt.u32.u64 %0, t; }"
        : "=r"(a) : "l"(p));
    return a;
}
__device__ __forceinline__ uint32_t cvt_tf32(float v) {
    uint32_t r;
    asm("cvt.rna.tf32.f32 %0, %1;" : "=r"(r) : "f"(v));
    return r;
}
// hi via cvt.rna; lo passed as raw fp32 bits (HMMA truncates low mantissa)
__device__ __forceinline__ void split2(float v, uint32_t& hi, uint32_t& lo) {
    hi = cvt_tf32(v);
    lo = __float_as_uint(v - __uint_as_float(hi));
}
// D += A*B, m16n8k8 tf32
__device__ __forceinline__ void mma8(float* c,
                                     uint32_t a0, uint32_t a1, uint32_t a2, uint32_t a3,
                                     uint32_t b0, uint32_t b1) {
    asm volatile(
        "mma.sync.aligned.m16n8k8.row.col.f32.tf32.tf32.f32 "
        "{%0,%1,%2,%3}, {%4,%5,%6,%7}, {%8,%9}, {%0,%1,%2,%3};"
        : "+f"(c[0]), "+f"(c[1]), "+f"(c[2]), "+f"(c[3])
        : "r"(a0), "r"(a1), "r"(a2), "r"(a3), "r"(b0), "r"(b1));
}
__device__ __forceinline__ void cp16(uint32_t saddr, const void* gptr) {
    asm volatile("cp.async.cg.shared.global [%0], [%1], 16;"
                 :: "r"(saddr), "l"(gptr) : "memory");
}
#define CP_COMMIT() asm volatile("cp.async.commit_group;" ::: "memory")
#define CP_WAIT(n)  asm volatile("cp.async.wait_group %0;" :: "n"(n) : "memory")

// ---------------------------------------------------------------------------
// Weight transposes + tf32 hi/lo pre-split (once per launch)
// ---------------------------------------------------------------------------
__global__ void transpose_qkv(const float* __restrict__ Wq,
                              const float* __restrict__ Wk,
                              const float* __restrict__ Wv)
{
    __shared__ float t[32][33];
    const int z = blockIdx.z >> 4;
    const int h = blockIdx.z & 15;
    const float* in = (z == 0 ? Wq : z == 1 ? Wk : Wv) + (size_t)h * D_ * DK_;
    const int j0 = blockIdx.x * 32;
    const int d0 = blockIdx.y * 32;
    const int tx = threadIdx.x, ty = threadIdx.y;
#pragma unroll
    for (int q = 0; q < 4; q++)
        t[ty + 8 * q][tx] = in[(size_t)(d0 + ty + 8 * q) * DK_ + j0 + tx];
    __syncthreads();
    const size_t ob = (size_t)z * D_ * D_ + (size_t)(h * 64 + j0) * D_ + d0;
#pragma unroll
    for (int q = 0; q < 4; q++) {
        const float v = t[tx][ty + 8 * q];
        const uint32_t hi = cvt_tf32(v);
        g_WThi[ob + (size_t)(ty + 8 * q) * D_ + tx] = __uint_as_float(hi);
        g_WTlo[ob + (size_t)(ty + 8 * q) * D_ + tx] = v - __uint_as_float(hi);
    }
}

__global__ void transpose_wo(const float* __restrict__ Wo)
{
    __shared__ float t[32][33];
    const int n0 = blockIdx.x * 32;
    const int j0 = blockIdx.y * 32;
    const int tx = threadIdx.x, ty = threadIdx.y;
#pragma unroll
    for (int q = 0; q < 4; q++)
        t[ty + 8 * q][tx] = Wo[(size_t)(j0 + ty + 8 * q) * D_ + n0 + tx];
    __syncthreads();
#pragma unroll
    for (int q = 0; q < 4; q++) {
        const float v = t[tx][ty + 8 * q];
        const uint32_t hi = cvt_tf32(v);
        g_WoThi[(size_t)(n0 + ty + 8 * q) * D_ + j0 + tx] = __uint_as_float(hi);
        g_WoTlo[(size_t)(n0 + ty + 8 * q) * D_ + j0 + tx] = v - __uint_as_float(hi);
    }
}

// ---------------------------------------------------------------------------
// GEMM: 128x128x32 CTA tile, 4 warps (2x2), warp tile 64x64, cp.async 2-stage.
// B operand pre-split: smem holds A (fp32) + Bhi + Blo planes. 2 CTAs/SM.
// ---------------------------------------------------------------------------
#define GPAD 36
#define GEMM_SMEM (2 * 3 * 128 * GPAD * 4)   // 110592 B

__device__ __forceinline__ void gemm_chunk4(const float (*As)[GPAD],
                                            const float (*Bhs)[GPAD],
                                            const float (*Bls)[GPAD],
                                            int wm, int wn, int g, int t,
                                            float c[4][8][4])
{
#pragma unroll
    for (int ks = 0; ks < 4; ks++) {
        const int kc = ks * 8;
        uint32_t ah[4][4], al[4][4];
#pragma unroll
        for (int mf = 0; mf < 4; mf++) {
            const int r = wm * 64 + mf * 16;
            split2(As[r + g][kc + t],          ah[mf][0], al[mf][0]);
            split2(As[r + g + 8][kc + t],      ah[mf][1], al[mf][1]);
            split2(As[r + g][kc + t + 4],      ah[mf][2], al[mf][2]);
            split2(As[r + g + 8][kc + t + 4],  ah[mf][3], al[mf][3]);
        }
#pragma unroll
        for (int nf = 0; nf < 8; nf++) {
            const int n = wn * 64 + nf * 8;
            const uint32_t bh0 = __float_as_uint(Bhs[n + g][kc + t]);
            const uint32_t bh1 = __float_as_uint(Bhs[n + g][kc + t + 4]);
            const uint32_t bl0 = __float_as_uint(Bls[n + g][kc + t]);
            const uint32_t bl1 = __float_as_uint(Bls[n + g][kc + t + 4]);
#pragma unroll
            for (int mf = 0; mf < 4; mf++) {
                mma8(c[mf][nf], ah[mf][0], ah[mf][1], ah[mf][2], ah[mf][3], bh0, bh1);
                mma8(c[mf][nf], ah[mf][0], ah[mf][1], ah[mf][2], ah[mf][3], bl0, bl1);
                mma8(c[mf][nf], al[mf][0], al[mf][1], al[mf][2], al[mf][3], bh0, bh1);
            }
        }
    }
}

// ---------------------------------------------------------------------------
// QKV projection. Epilogue: z=0 -> g_Q (fp32); z=1 -> K split planes [bh][kv][d];
// z=2 -> V split planes TRANSPOSED [bh][d][kv].
// ---------------------------------------------------------------------------
__global__ __launch_bounds__(128, 2) void qkv_mma(
    const float* __restrict__ x,
    const float* __restrict__ bq, const float* __restrict__ bk,
    const float* __restrict__ bv)
{
    extern __shared__ float sm[];
    float (*Asm)[GPAD]  = (float(*)[GPAD])sm;
    float (*Bhsm)[GPAD] = (float(*)[GPAD])(sm + 2 * 128 * GPAD);
    float (*Blsm)[GPAD] = (float(*)[GPAD])(sm + 4 * 128 * GPAD);

    const int tid = threadIdx.x;
    const int wid = tid >> 5;
    const int lane = tid & 31;
    const int g = lane >> 2, t = lane & 3;
    const int wm = wid >> 1, wn = wid & 1;
    const int m0 = blockIdx.x * 128;
    const int n0 = blockIdx.y * 128;
    const int z  = blockIdx.z;

    const float* Bth = g_WThi + (size_t)z * D_ * D_;
    const float* Btl = g_WTlo + (size_t)z * D_ * D_;
    const float* bias = (z == 0) ? bq : (z == 1) ? bk : bv;

    const int lr = tid >> 3;          // 0..15 (x8 -> 128 rows)
    const int lc = (tid & 7) * 4;

    const uint32_t aB  = smem_u32(sm);
    const uint32_t bhB = aB + 2 * 128 * GPAD * 4;
    const uint32_t blB = aB + 4 * 128 * GPAD * 4;

#pragma unroll
    for (int i = 0; i < 8; i++) {
        const int r = lr + i * 16;
        cp16(aB  + (uint32_t)(r * GPAD + lc) * 4, &x  [(size_t)(m0 + r) * D_ + lc]);
        cp16(bhB + (uint32_t)(r * GPAD + lc) * 4, &Bth[(size_t)(n0 + r) * D_ + lc]);
        cp16(blB + (uint32_t)(r * GPAD + lc) * 4, &Btl[(size_t)(n0 + r) * D_ + lc]);
    }
    CP_COMMIT();

    float c[4][8][4];
#pragma unroll
    for (int a = 0; a < 4; a++)
#pragma unroll
        for (int b = 0; b < 8; b++)
#pragma unroll
            for (int q = 0; q < 4; q++) c[a][b][q] = 0.0f;

    for (int ch = 0; ch < 32; ch++) {
        const int s = ch & 1;
        if (ch + 1 < 32) {
            const int k0 = (ch + 1) * 32;
            const uint32_t so = (uint32_t)((ch + 1) & 1) * 128 * GPAD * 4;
#pragma unroll
            for (int i = 0; i < 8; i++) {
                const int r = lr + i * 16;
                cp16(aB  + so + (uint32_t)(r * GPAD + lc) * 4,
                     &x  [(size_t)(m0 + r) * D_ + k0 + lc]);
                cp16(bhB + so + (uint32_t)(r * GPAD + lc) * 4,
                     &Bth[(size_t)(n0 + r) * D_ + k0 + lc]);
                cp16(blB + so + (uint32_t)(r * GPAD + lc) * 4,
                     &Btl[(size_t)(n0 + r) * D_ + k0 + lc]);
            }
            CP_COMMIT();
            CP_WAIT(1);
        } else {
            CP_WAIT(0);
        }
        __syncthreads();
        gemm_chunk4(&Asm[s * 128], &Bhsm[s * 128], &Blsm[s * 128], wm, wn, g, t, c);
        __syncthreads();
    }

#pragma unroll
    for (int mf = 0; mf < 4; mf++) {
#pragma unroll
        for (int nf = 0; nf < 8; nf++) {
            const int j = n0 + wn * 64 + nf * 8 + 2 * t;
            const int head = j >> 6, kin = j & 63;
            const float bz0 = bias[j], bz1 = bias[j + 1];
#pragma unroll
            for (int rr = 0; rr < 2; rr++) {
                const int m = m0 + wm * 64 + mf * 16 + g + rr * 8;
                const int b = m >> 11, sidx = m & 2047;
                const int bh = b * H_ + head;
                const float v0 = c[mf][nf][rr * 2] + bz0;
                const float v1 = c[mf][nf][rr * 2 + 1] + bz1;
                if (z == 0) {
                    float* p = g_Q + ((size_t)bh * S_ + sidx) * DK_ + kin;
                    *(float2*)p = make_float2(v0, v1);
                } else if (z == 1) {
                    uint32_t h0, l0, h1, l1;
                    split2(v0, h0, l0); split2(v1, h1, l1);
                    const size_t p = ((size_t)bh * S_ + sidx) * DK_ + kin;
                    *(float2*)&g_Khi[p] = make_float2(__uint_as_float(h0),
                                                      __uint_as_float(h1));
                    *(float2*)&g_Klo[p] = make_float2(__uint_as_float(l0),
                                                      __uint_as_float(l1));
                } else {
                    uint32_t h0, l0, h1, l1;
                    split2(v0, h0, l0); split2(v1, h1, l1);
                    const size_t p = ((size_t)bh * DK_ + kin) * S_ + sidx;  // [bh][d][kv]
                    g_Vhi[p]      = __uint_as_float(h0);
                    g_Vlo[p]      = __uint_as_float(l0);
                    g_Vhi[p + S_] = __uint_as_float(h1);
                    g_Vlo[p + S_] = __uint_as_float(l1);
                }
            }
        }
    }
}

// ---------------------------------------------------------------------------
// Output projection (unchanged from R12)
// ---------------------------------------------------------------------------
__global__ __launch_bounds__(128, 2) void out_mma(
    const float* __restrict__ bo, float* __restrict__ out)
{
    extern __shared__ float sm[];
    float (*Asm)[GPAD]  = (float(*)[GPAD])sm;
    float (*Bhsm)[GPAD] = (float(*)[GPAD])(sm + 2 * 128 * GPAD);
    float (*Blsm)[GPAD] = (float(*)[GPAD])(sm + 4 * 128 * GPAD);

    const int tid = threadIdx.x;
    const int wid = tid >> 5;
    const int lane = tid & 31;
    const int g = lane >> 2, t = lane & 3;
    const int wm = wid >> 1, wn = wid & 1;
    const int m0 = blockIdx.x * 128;
    const int n0 = blockIdx.y * 128;
    const int bb = m0 >> 11;
    const int sbase = m0 & 2047;

    const int lr = tid >> 3;
    const int lc = (tid & 7) * 4;

    const uint32_t aB  = smem_u32(sm);
    const uint32_t bhB = aB + 2 * 128 * GPAD * 4;
    const uint32_t blB = aB + 4 * 128 * GPAD * 4;

#pragma unroll
    for (int i = 0; i < 8; i++) {
        const int r = lr + i * 16;
        const float* src = g_O + ((size_t)(bb * H_) * S_ + sbase + r) * DK_ + lc;
        cp16(aB  + (uint32_t)(r * GPAD + lc) * 4, src);
        cp16(bhB + (uint32_t)(r * GPAD + lc) * 4, &g_WoThi[(size_t)(n0 + r) * D_ + lc]);
        cp16(blB + (uint32_t)(r * GPAD + lc) * 4, &g_WoTlo[(size_t)(n0 + r) * D_ + lc]);
    }
    CP_COMMIT();

    float c[4][8][4];
#pragma unroll
    for (int a = 0; a < 4; a++)
#pragma unroll
        for (int b = 0; b < 8; b++)
#pragma unroll
            for (int q = 0; q < 4; q++) c[a][b][q] = 0.0f;

    for (int ch = 0; ch < 32; ch++) {
        const int s = ch & 1;
        if (ch + 1 < 32) {
            const int k0 = (ch + 1) * 32;
            const int head = k0 >> 6, kin = k0 & 63;
            const uint32_t so = (uint32_t)((ch + 1) & 1) * 128 * GPAD * 4;
#pragma unroll
            for (int i = 0; i < 8; i++) {
                const int r = lr + i * 16;
                const float* src = g_O +
                    ((size_t)(bb * H_ + head) * S_ + sbase + r) * DK_ + kin + lc;
                cp16(aB  + so + (uint32_t)(r * GPAD + lc) * 4, src);
                cp16(bhB + so + (uint32_t)(r * GPAD + lc) * 4,
                     &g_WoThi[(size_t)(n0 + r) * D_ + k0 + lc]);
                cp16(blB + so + (uint32_t)(r * GPAD + lc) * 4,
                     &g_WoTlo[(size_t)(n0 + r) * D_ + k0 + lc]);
            }
            CP_COMMIT();
            CP_WAIT(1);
        } else {
            CP_WAIT(0);
        }
        __syncthreads();
        gemm_chunk4(&Asm[s * 128], &Bhsm[s * 128], &Blsm[s * 128], wm, wn, g, t, c);
        __syncthreads();
    }

#pragma unroll
    for (int mf = 0; mf < 4; mf++) {
#pragma unroll
        for (int nf = 0; nf < 8; nf++) {
            const int j = n0 + wn * 64 + nf * 8 + 2 * t;
            const float bz0 = bo[j], bz1 = bo[j + 1];
#pragma unroll
            for (int rr = 0; rr < 2; rr++) {
                const int m = m0 + wm * 64 + mf * 16 + g + rr * 8;
                *(float2*)&out[(size_t)m * D_ + j] =
                    make_float2(c[mf][nf][rr * 2] + bz0, c[mf][nf][rr * 2 + 1] + bz1);
            }
        }
    }
}

// ---------------------------------------------------------------------------
// Causal flash attention v5: pre-split K/V planes streamed via cp.async,
// double-buffered. 256 threads (8 warps), q-tile 128, kv-tile 64.
// Smem: Qs[128] + Ps[128] + 2 stages x {Khi,Klo,Vhi,Vlo}[64], APAD=68.
// No split work and no staging registers in the kv loop.
// ---------------------------------------------------------------------------
#define APAD 68
#define PLANE_B (64 * APAD * 4)              // 17408 B per plane
#define STAGE_B (4 * PLANE_B)                // 69632 B per stage
#define ATTN_SMEM ((256 * APAD * 4) + 2 * STAGE_B)   // 208896 B

__global__ __launch_bounds__(256) void attn_cp()
{
    extern __shared__ float sm[];
    float (*Qs)[APAD] = (float(*)[APAD])sm;        // [128] fp32 scaled Q
    float (*Ps)[APAD] = Qs + 128;                  // [128] P values
    float* kvf = sm + 256 * APAD;                  // stage planes base (float*)

    const int qb = (int)(gridDim.x - 1) - (int)blockIdx.x;   // big tiles first
    const int bh = blockIdx.y;
    const float* Qp   = g_Q   + (size_t)bh * S_ * DK_;
    const float* Khip = g_Khi + (size_t)bh * S_ * DK_;
    const float* Klop = g_Klo + (size_t)bh * S_ * DK_;
    const float* Vhip = g_Vhi + (size_t)bh * S_ * DK_;   // [d][kv]
    const float* Vlop = g_Vlo + (size_t)bh * S_ * DK_;
    float*       Op   = g_O   + (size_t)bh * S_ * DK_;

    const int tid = threadIdx.x;
    const int wid = tid >> 5;
    const int lane = tid & 31;
    const int g = lane >> 2, t = lane & 3;
    const int wrow = wid * 16;
    const int q0 = qb * 128;
    const int ntiles = 2 * qb + 2;

    const uint32_t kvB = smem_u32(sm) + 256 * APAD * 4;

    // ---- stage Q (scaled by 1/8) ----
    {
        const int r = tid >> 1;
        const int c0 = (tid & 1) * 32;
#pragma unroll
        for (int i = 0; i < 8; i++) {
            float4 q = *(const float4*)&Qp[(size_t)(q0 + r) * DK_ + c0 + 4 * i];
            Qs[r][c0 + 4 * i + 0] = q.x * 0.125f;
            Qs[r][c0 + 4 * i + 1] = q.y * 0.125f;
            Qs[r][c0 + 4 * i + 2] = q.z * 0.125f;
            Qs[r][c0 + 4 * i + 3] = q.w * 0.125f;
        }
    }

    // cp.async issue for one stage: 16 cp16/thread (4 per plane)
    auto issue_stage = [&](int st, int kv0) {
        const uint32_t sb = kvB + (uint32_t)st * STAGE_B;
#pragma unroll
        for (int i = 0; i < 4; i++) {
            const int idx = tid + 256 * i;     // 0..1023
            const int r  = idx >> 4;           // 0..63
            const int c4 = (idx & 15) * 4;     // 0..60
            const uint32_t soff = (uint32_t)(r * APAD + c4) * 4;
            cp16(sb + 0 * PLANE_B + soff, Khip + (size_t)(kv0 + r) * DK_ + c4);
            cp16(sb + 1 * PLANE_B + soff, Klop + (size_t)(kv0 + r) * DK_ + c4);
            cp16(sb + 2 * PLANE_B + soff, Vhip + (size_t)r * S_ + kv0 + c4);
            cp16(sb + 3 * PLANE_B + soff, Vlop + (size_t)r * S_ + kv0 + c4);
        }
    };

    float cO[8][4];
#pragma unroll
    for (int nf = 0; nf < 8; nf++)
#pragma unroll
        for (int q = 0; q < 4; q++) cO[nf][q] = 0.0f;
    float m0v = -1e30f, m1v = -1e30f, l0 = 0.0f, l1 = 0.0f;

    // prologue: stage 0
    issue_stage(0, 0);
    CP_COMMIT();

    for (int kt = 0; kt < ntiles; kt++) {
        const int kv0 = kt * 64;
        const int st  = kt & 1;

        CP_WAIT(0);        // stage st landed
        __syncthreads();   // visible to all; prior compute on st^1 done

        if (kt + 1 < ntiles) {
            issue_stage(st ^ 1, kv0 + 64);
            CP_COMMIT();
        }

        // warps fully above this kv tile skip compute (barriers already passed)
        if (kv0 <= q0 + wrow + 15) {
            const float (*Khi)[APAD] = (const float(*)[APAD])(kvf + st * (STAGE_B / 4));
            const float (*Klo)[APAD] = Khi + 64;
            const float (*Vhi)[APAD] = Klo + 64;
            const float (*Vlo)[APAD] = Vhi + 64;

            // ---- S = Q K^T (tf32 x3) ----
            float cS[8][4];
#pragma unroll
            for (int nf = 0; nf < 8; nf++)
#pragma unroll
                for (int q = 0; q < 4; q++) cS[nf][q] = 0.0f;

#pragma unroll
            for (int ks = 0; ks < 8; ks++) {
                const int kc = ks * 8;
                uint32_t ah[4], al[4];
                split2(Qs[wrow + g][kc + t],         ah[0], al[0]);
                split2(Qs[wrow + g + 8][kc + t],     ah[1], al[1]);
                split2(Qs[wrow + g][kc + t + 4],     ah[2], al[2]);
                split2(Qs[wrow + g + 8][kc + t + 4], ah[3], al[3]);
#pragma unroll
                for (int nf = 0; nf < 8; nf++) {
                    const uint32_t bh0 = __float_as_uint(Khi[nf * 8 + g][kc + t]);
                    const uint32_t bh1 = __float_as_uint(Khi[nf * 8 + g][kc + t + 4]);
                    const uint32_t bl0 = __float_as_uint(Klo[nf * 8 + g][kc + t]);
                    const uint32_t bl1 = __float_as_uint(Klo[nf * 8 + g][kc + t + 4]);
                    mma8(cS[nf], ah[0], ah[1], ah[2], ah[3], bh0, bh1);
                    mma8(cS[nf], ah[0], ah[1], ah[2], ah[3], bl0, bl1);
                    mma8(cS[nf], al[0], al[1], al[2], al[3], bh0, bh1);
                }
            }

            // ---- causal mask ----
            if (kv0 + 63 > q0 + wrow) {
                const int r0g = q0 + wrow + g;
                const int r1g = r0g + 8;
#pragma unroll
                for (int nf = 0; nf < 8; nf++) {
                    const int col = kv0 + nf * 8 + 2 * t;
                    if (col     > r0g) cS[nf][0] = -1e30f;
                    if (col + 1 > r0g) cS[nf][1] = -1e30f;
                    if (col     > r1g) cS[nf][2] = -1e30f;
                    if (col + 1 > r1g) cS[nf][3] = -1e30f;
                }
            }

            // ---- online softmax ----
            float mx0 = -1e30f, mx1 = -1e30f;
#pragma unroll
            for (int nf = 0; nf < 8; nf++) {
                mx0 = fmaxf(mx0, fmaxf(cS[nf][0], cS[nf][1]));
                mx1 = fmaxf(mx1, fmaxf(cS[nf][2], cS[nf][3]));
            }
            mx0 = fmaxf(mx0, __shfl_xor_sync(0xffffffffu, mx0, 1));
            mx0 = fmaxf(mx0, __shfl_xor_sync(0xffffffffu, mx0, 2));
            mx1 = fmaxf(mx1, __shfl_xor_sync(0xffffffffu, mx1, 1));
            mx1 = fmaxf(mx1, __shfl_xor_sync(0xffffffffu, mx1, 2));
            const float mn0 = fmaxf(m0v, mx0), mn1 = fmaxf(m1v, mx1);
            const float corr0 = __expf(m0v - mn0), corr1 = __expf(m1v - mn1);
            float rs0 = 0.0f, rs1 = 0.0f;
#pragma unroll
            for (int nf = 0; nf < 8; nf++) {
                const float p0 = __expf(cS[nf][0] - mn0);
                const float p1 = __expf(cS[nf][1] - mn0);
                const float p2 = __expf(cS[nf][2] - mn1);
                const float p3 = __expf(cS[nf][3] - mn1);
                rs0 += p0 + p1; rs1 += p2 + p3;
                *(float2*)&Ps[wrow + g][nf * 8 + 2 * t]     = make_float2(p0, p1);
                *(float2*)&Ps[wrow + g + 8][nf * 8 + 2 * t] = make_float2(p2, p3);
            }
            rs0 += __shfl_xor_sync(0xffffffffu, rs0, 1);
            rs0 += __shfl_xor_sync(0xffffffffu, rs0, 2);
            rs1 += __shfl_xor_sync(0xffffffffu, rs1, 1);
            rs1 += __shfl_xor_sync(0xffffffffu, rs1, 2);
            l0 = l0 * corr0 + rs0; l1 = l1 * corr1 + rs1;
            m0v = mn0; m1v = mn1;
#pragma unroll
            for (int nf = 0; nf < 8; nf++) {
                cO[nf][0] *= corr0; cO[nf][1] *= corr0;
                cO[nf][2] *= corr1; cO[nf][3] *= corr1;
            }
            __syncwarp();   // P rows visible within the owning warp

            // ---- O += P V (tf32 x3) ----
#pragma unroll
            for (int ks = 0; ks < 8; ks++) {
                const int kc = ks * 8;
                uint32_t ah[4], al[4];
                split2(Ps[wrow + g][kc + t],         ah[0], al[0]);
                split2(Ps[wrow + g + 8][kc + t],     ah[1], al[1]);
                split2(Ps[wrow + g][kc + t + 4],     ah[2], al[2]);
                split2(Ps[wrow + g + 8][kc + t + 4], ah[3], al[3]);
#pragma unroll
                for (int nf = 0; nf < 8; nf++) {
                    const uint32_t bh0 = __float_as_uint(Vhi[nf * 8 + g][kc + t]);
                    const uint32_t bh1 = __float_as_uint(Vhi[nf * 8 + g][kc + t + 4]);
                    const uint32_t bl0 = __float_as_uint(Vlo[nf * 8 + g][kc + t]);
                    const uint32_t bl1 = __float_as_uint(Vlo[nf * 8 + g][kc + t + 4]);
                    mma8(cO[nf], ah[0], ah[1], ah[2], ah[3], bh0, bh1);
                    mma8(cO[nf], ah[0], ah[1], ah[2], ah[3], bl0, bl1);
                    mma8(cO[nf], al[0], al[1], al[2], al[3], bh0, bh1);
                }
            }
        }
    }

    // ---- normalize + store O ----
    const float inv0 = 1.0f / l0, inv1 = 1.0f / l1;
#pragma unroll
    for (int nf = 0; nf < 8; nf++) {
        const int col = nf * 8 + 2 * t;
        *(float2*)&Op[(size_t)(q0 + wrow + g) * DK_ + col] =
            make_float2(cO[nf][0] * inv0, cO[nf][1] * inv0);
        *(float2*)&Op[(size_t)(q0 + wrow + g + 8) * DK_ + col] =
            make_float2(cO[nf][2] * inv1, cO[nf][3] * inv1);
    }
}

// ---------------------------------------------------------------------------
extern "C" void kernel_launch(void* const* d_in, const int* in_sizes, int n_in,
                              void* d_out, int out_size)
{
    const float* x  = (const float*)d_in[0];
    const float* Wq = (const float*)d_in[2];
    const float* bq = (const float*)d_in[3];
    const float* Wk = (const float*)d_in[4];
    const float* bk = (const float*)d_in[5];
    const float* Wv = (const float*)d_in[6];
    const float* bv = (const float*)d_in[7];
    const float* Wo = (const float*)d_in[8];
    const float* bo = (const float*)d_in[9];
    float* out = (float*)d_out;

    cudaFuncSetAttribute(qkv_mma, cudaFuncAttributeMaxDynamicSharedMemorySize, GEMM_SMEM);
    cudaFuncSetAttribute(out_mma, cudaFuncAttributeMaxDynamicSharedMemorySize, GEMM_SMEM);
    cudaFuncSetAttribute(attn_cp, cudaFuncAttributeMaxDynamicSharedMemorySize, ATTN_SMEM);

    transpose_qkv<<<dim3(2, 32, 48), dim3(32, 8)>>>(Wq, Wk, Wv);
    transpose_wo<<<dim3(32, 32), dim3(32, 8)>>>(Wo);

    qkv_mma<<<dim3(M_ / 128, D_ / 128, 3), 128, GEMM_SMEM>>>(x, bq, bk, bv);

    attn_cp<<<dim3(S_ / 128, B_ * H_), 256, ATTN_SMEM>>>();

    out_mma<<<dim3(M_ / 128, D_ / 128), 128, GEMM_SMEM>>>(bo, out);
}